// round 17
// baseline (speedup 1.0000x reference)
#include <cuda_runtime.h>
#include <cuda_fp16.h>
#include <math.h>

#define BATCH 4
#define CH    128
#define HH    384
#define WW    384
#define HW    (HH*WW)          // 147456
#define NPIX  (BATCH*HW)

#define MAXSEL ((HH-4)*(WW-4)*BATCH)      // 577600
#define CTX_BLOCKS ((MAXSEL + 31) / 32)   // 8 warps/block, 4 px/warp

// Scratch (allocation-free: __device__ globals; zero-initialized at load,
// re-zeroed by the finalize block at the end of every run)
__device__ unsigned char g_T8[(size_t)NPIX * CH]; // [B,H,W,C] int8 features (75 MB)
__device__ float         g_inv[NPIX];             // s_p / max(||f_p||,1e-8)
__device__ unsigned char g_cls[NPIX];
__device__ int           g_list[NPIX];
__device__ int           g_nsel;
__device__ float         g_acc[BATCH];
__device__ int           g_cnt[BATCH];
__device__ int           g_bnd[BATCH];
__device__ int           g_done;

__device__ __forceinline__ unsigned pack4(int a, int b, int c, int d) {
    return (a & 0xff) | ((b & 0xff) << 8) | ((c & 0xff) << 16) | ((d & 0xff) << 24);
}

// packed-merge step: combine two distributed values a,b over lane pairs (xor m).
__device__ __forceinline__ float bmerge(float a, float b, bool sel, int m) {
    float keep = sel ? b : a;
    float send = sel ? a : b;
    return keep + __shfl_xor_sync(0xffffffffu, send, m);
}

// ---------------------------------------------------------------------------
// 1. transpose [B,C,H,W] -> [B,H,W,C] int8 (per-pixel max-abs scale),
//    fused fp32 norm + scale -> g_inv, prep (mask/compaction/class).
__global__ void transpose_kernel(const float* __restrict__ er,
                                 const int* __restrict__ seg,
                                 const int* __restrict__ gtb) {
    __shared__ float tile[128][33];   // whole 32px x 128ch block
    __shared__ float red[8][32];
    __shared__ float rmx[8][32];
    __shared__ float sinv[32];        // 127/maxabs per pixel
    int tx = threadIdx.x, ty = threadIdx.y;
    int t  = ty * 32 + tx;
    int p0 = blockIdx.x * 32;
    int b  = blockIdx.y;
    int px  = t >> 3;                 // output pixel 0..31
    int oct = t & 7;                  // 8-byte group within 64-ch chunk

    uint2* out2 = (uint2*)g_T8 + ((size_t)(b * HW) + p0) * 16;

    float sq = 0.0f, mx = 0.0f;
#pragma unroll
    for (int i = 0; i < 16; i++) {    // 16 independent LDGs up-front (MLP)
        int c = ty + 8 * i;
        float v = er[((size_t)(b * CH + c)) * HW + p0 + tx];  // 128B coalesced
        tile[c][tx] = v;
        sq += v * v;
        mx = fmaxf(mx, fabsf(v));
    }
    red[ty][tx] = sq;
    rmx[ty][tx] = mx;
    __syncthreads();

    if (ty == 0) {   // warp 0: norms, scales, prep for this block's 32 pixels
        float s = 0.0f, m = 0.0f;
#pragma unroll
        for (int k = 0; k < 8; k++) { s += red[k][tx]; m = fmaxf(m, rmx[k][tx]); }
        int rem = p0 + tx;
        int p   = b * HW + rem;
        sinv[tx] = (m > 0.0f) ? 127.0f / m : 0.0f;
        g_inv[p] = (m * (1.0f / 127.0f)) / fmaxf(sqrtf(s), 1e-8f);

        int y = rem / WW;
        int x = rem - y * WW;
        int s1r = seg[((size_t)(b * 2 + 1)) * HW + rem];
        int gt  = gtb[p];            if (gt == 255) gt = 0;
        int s1  = s1r;               if (s1 == 255) s1 = 0;
        bool bnd = (gt * s1) > 0;
        bool inter = (y >= 2) && (y <= HH - 3) && (x >= 2) && (x <= WW - 3);
        bool sel = bnd && inter;
        g_cls[p] = (unsigned char)s1r;

        unsigned selm = __ballot_sync(0xffffffffu, sel);
        unsigned bndm = __ballot_sync(0xffffffffu, bnd);
        int base = 0;
        if (tx == 0 && selm) {
            base = atomicAdd(&g_nsel, __popc(selm));
            atomicAdd(&g_cnt[b], __popc(selm));
        }
        if (tx == 0 && bndm) atomicOr(&g_bnd[b], 1);
        base = __shfl_sync(0xffffffffu, base, 0);
        if (sel) g_list[base + __popc(selm & ((1u << tx) - 1u))] = p;
    }
    __syncthreads();

    float is = sinv[px];
#pragma unroll
    for (int h = 0; h < 2; h++) {     // both 64-channel chunks from the tile
        int q[8];
#pragma unroll
        for (int m = 0; m < 8; m++)
            q[m] = __float2int_rn(tile[64 * h + 8 * oct + m][px] * is);
        uint2 v;
        v.x = pack4(q[0], q[1], q[2], q[3]);
        v.y = pack4(q[4], q[5], q[6], q[7]);
        out2[(size_t)px * 16 + 8 * h + oct] = v;
    }
}

// ---------------------------------------------------------------------------
// 2. main: 4 pixels/warp, 8 lanes/pixel; one LDG.128 per neighbor covers the
//    full 128-int8 pixel; 4x DP4A per lane-dot; packed-merge butterflies;
//    fused finalize
__global__ void __launch_bounds__(256, 6)
ctx_kernel(float* __restrict__ out) {
    constexpr int OFF[24] = {
        -770,-769,-768,-767,-766,
        -386,-385,-384,-383,-382,
          -2,  -1,   1,   2,
         382, 383, 384, 385, 386,
         766, 767, 768, 769, 770 };

    __shared__ float sacc[BATCH];
    int tid  = threadIdx.x;
    int nsel = g_nsel;

    if (blockIdx.x * 32 < nsel) {
        if (tid < BATCH) sacc[tid] = 0.0f;
        __syncthreads();

        int warp = blockIdx.x * 8 + (tid >> 5);
        int lane = tid & 31;
        int grp  = lane >> 3;               // pixel within warp (0..3)
        int sub  = lane & 7;                // lane within pixel (0..7)
        bool b0 = sub & 1, b1 = sub & 2, b2 = sub & 4;

        int idx = warp * 4 + grp;
        bool active = idx < nsel;
        int p = active ? g_list[idx] : (2 * WW + 2);

        const unsigned char* pbase = g_T8 + (size_t)p * CH + sub * 16;
        int4 cv = *(const int4*)pbase;       // center: 16 int8 per lane
        float invc = g_inv[p];
        unsigned char cp = g_cls[p];

        float acc = 0.0f;
#pragma unroll
        for (int g = 0; g < 3; g++) {
            float dots[8];
#pragma unroll
            for (int jj = 0; jj < 8; jj++) {
                int4 nv = *(const int4*)(pbase + OFF[g * 8 + jj] * CH);
                int d = __dp4a(nv.x, cv.x, 0);
                d = __dp4a(nv.y, cv.y, d);
                d = __dp4a(nv.z, cv.z, d);
                d = __dp4a(nv.w, cv.w, d);
                dots[jj] = (float)d;         // exact: |d| < 2^21
            }
            // packed-merge reduction: lane sub ends with full sum of dots[sub]
            float t0 = bmerge(dots[0], dots[1], b0, 1);
            float t1 = bmerge(dots[2], dots[3], b0, 1);
            float t2 = bmerge(dots[4], dots[5], b0, 1);
            float t3 = bmerge(dots[6], dots[7], b0, 1);
            float u0 = bmerge(t0, t1, b1, 2);
            float u1 = bmerge(t2, t3, b1, 2);
            float w  = bmerge(u0, u1, b2, 4);

            if (active) {
                int q = p + OFF[g * 8 + sub];
                float cosv = w * invc * g_inv[q];
                float lab  = (g_cls[q] == cp) ? 1.0f : 0.0f;
                float e = cosv - lab;
                acc += e * e;
            }
        }
#pragma unroll
        for (int m = 1; m <= 4; m <<= 1)
            acc += __shfl_xor_sync(0xffffffffu, acc, m);
        if (sub == 0 && active) atomicAdd(&sacc[p / HW], acc);

        __syncthreads();
        if (tid < BATCH) {
            float v = sacc[tid];
            if (v != 0.0f) atomicAdd(&g_acc[tid], v);
        }
        __syncthreads();
    }

    // fused finalize + state reset for the next graph replay
    if (tid == 0) {
        __threadfence();
        int done = atomicAdd(&g_done, 1);
        if (done == (int)gridDim.x - 1) {
            float tot = 0.0f, nv = 0.0f;
            for (int b = 0; b < BATCH; b++) {
                float lb = g_acc[b] / fmaxf((float)g_cnt[b], 1.0f) / 24.0f;
                if (g_bnd[b]) { tot += lb; nv += 1.0f; }
            }
            tot = tot / fmaxf(nv, 1.0f);
            if (isnan(tot)) tot = 0.0f;
            out[0] = tot;
            for (int b = 0; b < BATCH; b++) {
                g_acc[b] = 0.0f; g_cnt[b] = 0; g_bnd[b] = 0;
            }
            g_nsel = 0;
            __threadfence();
            g_done = 0;
        }
    }
}

// ---------------------------------------------------------------------------
extern "C" void kernel_launch(void* const* d_in, const int* in_sizes, int n_in,
                              void* d_out, int out_size) {
    const float* er  = (const float*)d_in[0];
    const int*   seg = (const int*)d_in[1];
    const int*   gtb = (const int*)d_in[2];
    float*       out = (float*)d_out;

    transpose_kernel<<<dim3(HW / 32, BATCH), dim3(32, 8)>>>(er, seg, gtb);
    ctx_kernel<<<CTX_BLOCKS, 256>>>(out);
}